// round 5
// baseline (speedup 1.0000x reference)
#include <cuda_runtime.h>
#include <cuda_fp16.h>

#define Bn   8
#define CHn  7
#define Hn   256
#define Wn   256
#define NBR  6
#define C1   64
#define PX   4

// Scratch for the "combined" (B,7,H,W) tensor between the two kernels.
__device__ float g_comb[Bn * CHn * Hn * Wn];

__device__ __forceinline__ __half2 u2h(unsigned u) {
    __half2 h;
    *reinterpret_cast<unsigned*>(&h) = u;
    return h;
}

// ---------------------------------------------------------------------------
// Kernel 1: one similarity branch per blockIdx.z, fp16x2 (HFMA2) math,
// fp32 epilogue (sigmoid + weighting).
// Smem per channel: 20 half2 (uint32) = base taps[9], check taps[9],
// (b1,b1), (w2,w2). 80 B/channel, 16B-aligned -> 5 LDS.128 per channel.
// ---------------------------------------------------------------------------
__global__ __launch_bounds__(256, 3) void branch_kernel(
    const float* __restrict__ x,
    const float* __restrict__ W1, const float* __restrict__ b1,
    const float* __restrict__ W2, const float* __restrict__ b2)
{
    __shared__ __align__(16) unsigned Wp[C1 * 20];   // 5120 B

    const int tid = threadIdx.y * 64 + threadIdx.x;
    const int n   = blockIdx.z;
    const int base_ic = (n < 3) ? 0 : 1;

    // Stage duplicated fp16 weights for this branch (base taps @0..8, check @9..17).
    for (int i = tid; i < C1 * 18; i += 256) {
        int c = i / 18, k = i % 18;
        float w = (k < 9)
            ? W1[(((n * C1 + c) * 2 + base_ic) * 9) + k]
            : W1[(((n * C1 + c) * 2 + (1 - base_ic)) * 9) + (k - 9)];
        __half h = __float2half_rn(w);
        __half2 hh = __halves2half2(h, h);
        Wp[c * 20 + k] = *reinterpret_cast<unsigned*>(&hh);
    }
    for (int c = tid; c < C1; c += 256) {
        __half hb = __float2half_rn(b1[n * C1 + c]);
        __half hw = __float2half_rn(W2[n * C1 + c]);
        __half2 b2h = __halves2half2(hb, hb);
        __half2 w2h = __halves2half2(hw, hw);
        Wp[c * 20 + 18] = *reinterpret_cast<unsigned*>(&b2h);
        Wp[c * 20 + 19] = *reinterpret_cast<unsigned*>(&w2h);
    }
    __syncthreads();

    const int b  = blockIdx.y;
    const int h  = blockIdx.x * 4 + threadIdx.y;
    const int w0 = threadIdx.x * PX;
    const int srcch = (n < 3) ? n : n + 1;

    // Load base + check 3x6 windows (zero-padded) in fp32.
    float bw[3][PX + 2], cw[3][PX + 2];
    {
        const float* xb = x + ((size_t)(b * CHn + 3)) * Hn * Wn;
        const float* xc = x + ((size_t)(b * CHn + srcch)) * Hn * Wn;
        #pragma unroll
        for (int r = 0; r < 3; r++) {
            int hh = h - 1 + r;
            bool hok = (hh >= 0) && (hh < Hn);
            #pragma unroll
            for (int c = 0; c < PX + 2; c++) {
                int ww = w0 - 1 + c;
                bool ok = hok && (ww >= 0) && (ww < Wn);
                bw[r][c] = ok ? __ldg(&xb[hh * Wn + ww]) : 0.f;
                cw[r][c] = ok ? __ldg(&xc[hh * Wn + ww]) : 0.f;
            }
        }
    }
    // Pack sliding-window pairs into half2: pair i = (win[i], win[i+1]).
    __half2 pb[3][5], pc[3][5];
    #pragma unroll
    for (int r = 0; r < 3; r++)
        #pragma unroll
        for (int i = 0; i < 5; i++) {
            pb[r][i] = __floats2half2_rn(bw[r][i], bw[r][i + 1]);
            pc[r][i] = __floats2half2_rn(cw[r][i], cw[r][i + 1]);
        }
    const float cen0 = cw[1][1], cen1 = cw[1][2], cen2 = cw[1][3], cen3 = cw[1][4];

    // Base passthrough channel (written once, by z==0 blocks).
    if (n == 0) {
        float4 bc = make_float4(bw[1][1], bw[1][2], bw[1][3], bw[1][4]);
        *(float4*)(g_comb + (((size_t)(b * CHn + 3)) * Hn + h) * Wn + w0) = bc;
    }

    const float bb2 = __ldg(&b2[n]);
    __half bb2h = __float2half_rn(bb2);
    __half2 sim01 = __halves2half2(bb2h, bb2h);
    __half2 sim23 = sim01;
    const __half2 zero2 = __floats2half2_rn(0.f, 0.f);

    #pragma unroll 2
    for (int c = 0; c < C1; c++) {
        unsigned wt[20];
        {
            const uint4* wq = (const uint4*)&Wp[c * 20];
            *(uint4*)&wt[0]  = wq[0];
            *(uint4*)&wt[4]  = wq[1];
            *(uint4*)&wt[8]  = wq[2];
            *(uint4*)&wt[12] = wq[3];
            *(uint4*)&wt[16] = wq[4];
        }
        __half2 ab01 = u2h(wt[18]), ab23 = ab01;   // base chain seeded with bias
        __half2 ac01 = zero2,       ac23 = zero2;  // check chain

        #pragma unroll
        for (int k = 0; k < 9; k++) {
            const int kh = k / 3, kw = k % 3;
            __half2 wbv = u2h(wt[k]);
            __half2 wcv = u2h(wt[9 + k]);
            ab01 = __hfma2(wbv, pb[kh][kw],     ab01);
            ab23 = __hfma2(wbv, pb[kh][kw + 2], ab23);
            ac01 = __hfma2(wcv, pc[kh][kw],     ac01);
            ac23 = __hfma2(wcv, pc[kh][kw + 2], ac23);
        }
        __half2 h01 = __hmax2(__hadd2(ab01, ac01), zero2);
        __half2 h23 = __hmax2(__hadd2(ab23, ac23), zero2);
        __half2 w2v = u2h(wt[19]);
        sim01 = __hfma2(w2v, h01, sim01);
        sim23 = __hfma2(w2v, h23, sim23);
    }

    float2 s01 = __half22float2(sim01);
    float2 s23 = __half22float2(sim23);
    float4 outv;
    outv.x = cen0 / (1.f + __expf(-s01.x));
    outv.y = cen1 / (1.f + __expf(-s01.y));
    outv.z = cen2 / (1.f + __expf(-s23.x));
    outv.w = cen3 / (1.f + __expf(-s23.y));
    *(float4*)(g_comb + (((size_t)(b * CHn + srcch)) * Hn + h) * Wn + w0) = outv;
}

// ---------------------------------------------------------------------------
// Kernel 2: final 7->7 3x3 SAME conv, fp32 (precision-critical 63-term sums).
// 128-thread blocks / 1024-block grid for occupancy.
// ---------------------------------------------------------------------------
__global__ __launch_bounds__(128) void mix_kernel(
    const float* __restrict__ Wm, const float* __restrict__ bm,
    float* __restrict__ out)
{
    __shared__ float Wms[7 * 7 * 9];
    __shared__ float bms[7];

    const int tid = threadIdx.y * 32 + threadIdx.x;
    for (int i = tid; i < 7 * 7 * 9; i += 128) Wms[i] = Wm[i];
    if (tid < 7) bms[tid] = bm[tid];
    __syncthreads();

    const int b  = blockIdx.y;
    const int h  = (blockIdx.x >> 1) * 4 + threadIdx.y;
    const int w0 = (blockIdx.x & 1) * 128 + threadIdx.x * PX;

    float acc[7][PX];
    #pragma unroll
    for (int o = 0; o < 7; o++) {
        const float bv = bms[o];
        #pragma unroll
        for (int p = 0; p < PX; p++) acc[o][p] = bv;
    }

    #pragma unroll 1
    for (int ic = 0; ic < 7; ic++) {
        const float* xp = g_comb + ((size_t)(b * CHn + ic)) * Hn * Wn;
        float win[3][PX + 2];
        #pragma unroll
        for (int r = 0; r < 3; r++) {
            int hh = h - 1 + r;
            bool hok = (hh >= 0) && (hh < Hn);
            #pragma unroll
            for (int c = 0; c < PX + 2; c++) {
                int ww = w0 - 1 + c;
                win[r][c] = (hok && ww >= 0 && ww < Wn) ? xp[hh * Wn + ww] : 0.f;
            }
        }
        #pragma unroll
        for (int o = 0; o < 7; o++) {
            #pragma unroll
            for (int kh = 0; kh < 3; kh++) {
                #pragma unroll
                for (int kw = 0; kw < 3; kw++) {
                    const float wv = Wms[(o * 7 + ic) * 9 + kh * 3 + kw];
                    #pragma unroll
                    for (int p = 0; p < PX; p++)
                        acc[o][p] = fmaf(wv, win[kh][kw + p], acc[o][p]);
                }
            }
        }
    }

    #pragma unroll
    for (int o = 0; o < 7; o++) {
        float4 v = make_float4(acc[o][0], acc[o][1], acc[o][2], acc[o][3]);
        *(float4*)(out + (((size_t)(b * CHn + o)) * Hn + h) * Wn + w0) = v;
    }
}

// ---------------------------------------------------------------------------
// kernel_launch: graph-capturable, allocation-free.
// Input order (metadata): x, W1, b1, W2, b2, Wm, bm
// ---------------------------------------------------------------------------
extern "C" void kernel_launch(void* const* d_in, const int* in_sizes, int n_in,
                              void* d_out, int out_size)
{
    const float* x  = (const float*)d_in[0];
    const float* W1 = (const float*)d_in[1];
    const float* b1 = (const float*)d_in[2];
    const float* W2 = (const float*)d_in[3];
    const float* b2 = (const float*)d_in[4];
    const float* Wm = (const float*)d_in[5];
    const float* bm = (const float*)d_in[6];
    float* out = (float*)d_out;

    dim3 blockB(64, 4, 1);
    dim3 gridB(Hn / 4, Bn, NBR);          // 64 row-tiles, 8 batches, 6 branches

    dim3 blockM(32, 4, 1);                 // 128 threads
    dim3 gridM((Hn / 4) * 2, Bn, 1);       // 128 x-tiles (2 col-halves * 64 row-tiles)

    branch_kernel<<<gridB, blockB>>>(x, W1, b1, W2, b2);
    mix_kernel<<<gridM, blockM>>>(Wm, bm, out);
}

// round 8
// speedup vs baseline: 2.3341x; 2.3341x over previous
#include <cuda_runtime.h>
#include <cuda_fp16.h>
#include <cstdint>

#define Bn   8
#define CHn  7
#define Hn   256
#define Wn   256
#define NBR  6
#define C1   64
#define PX   4

#define CTAS_PER_BRANCH 512
#define ITERS           16      // 512 CTAs * 4 warps * 16 px * 16 iters = 524288 px

// Scratch for the "combined" (B,7,H,W) tensor between the two kernels.
__device__ float g_comb[Bn * CHn * Hn * Wn];

__device__ __forceinline__ uint32_t smem_u32(const void* p) {
    uint32_t a;
    asm("{ .reg .u64 t; cvta.to.shared.u64 t, %1; cvt.u32.u64 %0, t; }" : "=r"(a) : "l"(p));
    return a;
}
__device__ __forceinline__ unsigned packh2(float lo, float hi) {
    __half2 h = __floats2half2_rn(lo, hi);
    return *reinterpret_cast<unsigned*>(&h);
}
__device__ __forceinline__ void ldmatrix_x4(uint32_t r[4], uint32_t addr) {
    asm volatile("ldmatrix.sync.aligned.m8n8.x4.shared.b16 {%0,%1,%2,%3}, [%4];"
                 : "=r"(r[0]), "=r"(r[1]), "=r"(r[2]), "=r"(r[3]) : "r"(addr));
}
__device__ __forceinline__ void ldmatrix_x2(uint32_t r[2], uint32_t addr) {
    asm volatile("ldmatrix.sync.aligned.m8n8.x2.shared.b16 {%0,%1}, [%2];"
                 : "=r"(r[0]), "=r"(r[1]) : "r"(addr));
}
__device__ __forceinline__ void mma16816(float c[4], const uint32_t a[4], const uint32_t b[2]) {
    asm volatile(
        "mma.sync.aligned.m16n8k16.row.col.f32.f16.f16.f32 "
        "{%0,%1,%2,%3}, {%4,%5,%6,%7}, {%8,%9}, {%0,%1,%2,%3};"
        : "+f"(c[0]), "+f"(c[1]), "+f"(c[2]), "+f"(c[3])
        : "r"(a[0]), "r"(a[1]), "r"(a[2]), "r"(a[3]), "r"(b[0]), "r"(b[1]));
}

// ---------------------------------------------------------------------------
// Branch kernel: warp-level HMMA implicit GEMM.
// A[16 px, 32 k] fp16: k0-8 base taps, k9 = 1.0 (bias lane), k10-15 = 0,
//                      k16-24 check taps, k25-31 = 0.
// B[64 ch, 32 k] fp16: k0-8 W1 base taps, k9 = b1[c], k16-24 W1 check taps.
// D fp32. Epilogue: relu, dot w2, quad-reduce, +b2, sigmoid, weight, store.
// Row stride 40 halves (80B): banks 20i mod 32 distinct -> ldmatrix conflict-free.
// ---------------------------------------------------------------------------
__global__ __launch_bounds__(128) void branch_kernel(
    const float* __restrict__ x,
    const float* __restrict__ W1, const float* __restrict__ b1,
    const float* __restrict__ W2, const float* __restrict__ b2)
{
    __shared__ __half Bs[C1 * 40];        // 5120 B
    __shared__ __half As[4][16 * 40];     // 4 x 1280 B
    __shared__ float  w2s[C1];
    __shared__ float  cenC[4][16], cenB[4][16];
    __shared__ float  sb2v;

    const int tid  = threadIdx.x;
    const int warp = tid >> 5;
    const int lane = tid & 31;
    const int n    = blockIdx.y;
    const int base_ic = (n < 3) ? 0 : 1;
    const int srcch   = (n < 3) ? n : n + 1;

    // ---- stage B (reordered, fp16) + w2 + b2 ----
    for (int i = tid; i < C1 * 40; i += 128) Bs[i] = __ushort_as_half(0);
    __syncthreads();
    for (int i = tid; i < C1 * 9; i += 128) {
        int c = i / 9, k = i % 9;
        Bs[c * 40 + k]      = __float2half_rn(W1[(((n * C1 + c) * 2 + base_ic) * 9) + k]);
        Bs[c * 40 + 16 + k] = __float2half_rn(W1[(((n * C1 + c) * 2 + (1 - base_ic)) * 9) + k]);
    }
    for (int c = tid; c < C1; c += 128) {
        Bs[c * 40 + 9] = __float2half_rn(b1[n * C1 + c]);
        w2s[c] = W2[n * C1 + c];
    }
    if (tid == 0) sb2v = b2[n];
    __syncthreads();

    // ---- load B fragments into registers (kept for whole kernel) ----
    uint32_t bf[8][2][2];
    {
        const uint32_t bbase = smem_u32(Bs);
        #pragma unroll
        for (int j = 0; j < 8; j++)
            #pragma unroll
            for (int s = 0; s < 2; s++) {
                int row = 8 * j + (lane & 7);
                uint32_t addr = bbase + (uint32_t)(row * 40 + s * 16) * 2
                              + (uint32_t)(((lane >> 3) & 1) * 16);
                ldmatrix_x2(bf[j][s], addr);
            }
    }
    // per-thread w2 values for owned columns
    float w2a[8], w2b[8];
    #pragma unroll
    for (int j = 0; j < 8; j++) {
        int n0 = 8 * j + 2 * (lane & 3);
        w2a[j] = w2s[n0];
        w2b[j] = w2s[n0 + 1];
    }
    const float my_b2 = sb2v;
    const uint32_t abase = smem_u32(&As[warp][0]);

    for (int it = 0; it < ITERS; it++) {
        const int pixbase = ((blockIdx.x + it * CTAS_PER_BRANCH) * 4 + warp) * 16;

        // ---- im2col: 2 threads per pixel (even: base ch, odd: check ch) ----
        const int p   = lane >> 1;
        const int pix = pixbase + p;
        const int b   = pix >> 16;
        const int hh0 = (pix >> 8) & 255;
        const int ww0 = pix & 255;
        const int ch  = (lane & 1) ? srcch : 3;
        const float* xs = x + ((size_t)(b * CHn + ch) << 16);

        float win[9];
        #pragma unroll
        for (int r = 0; r < 3; r++) {
            int hh = hh0 - 1 + r;
            bool hok = (hh >= 0) && (hh < Hn);
            #pragma unroll
            for (int cc = 0; cc < 3; cc++) {
                int ww = ww0 - 1 + cc;
                bool ok = hok && (ww >= 0) && (ww < Wn);
                win[r * 3 + cc] = ok ? __ldg(&xs[hh * Wn + ww]) : 0.f;
            }
        }

        unsigned hv[8];
        hv[0] = packh2(win[0], win[1]);
        hv[1] = packh2(win[2], win[3]);
        hv[2] = packh2(win[4], win[5]);
        hv[3] = packh2(win[6], win[7]);
        hv[4] = packh2(win[8], (lane & 1) ? 0.f : 1.0f);  // even gets bias lane k9
        hv[5] = hv[6] = hv[7] = 0u;

        {
            __half* Arow = &As[warp][p * 40 + (lane & 1) * 16];
            *reinterpret_cast<uint4*>(Arow)     = make_uint4(hv[0], hv[1], hv[2], hv[3]);
            *reinterpret_cast<uint4*>(Arow + 8) = make_uint4(hv[4], hv[5], hv[6], hv[7]);
        }
        if (lane & 1) cenC[warp][p] = win[4];
        else          cenB[warp][p] = win[4];
        __syncwarp();

        // ---- A fragments ----
        uint32_t a0[4], a1[4];
        {
            int row = lane & 15;
            uint32_t addr = abase + (uint32_t)(row * 40) * 2 + (uint32_t)((lane >> 4) * 16);
            ldmatrix_x4(a0, addr);        // k 0..15
            ldmatrix_x4(a1, addr + 32);   // k 16..31
        }

        // ---- 16 HMMA ----
        float c[8][4];
        #pragma unroll
        for (int j = 0; j < 8; j++) {
            c[j][0] = c[j][1] = c[j][2] = c[j][3] = 0.f;
            mma16816(c[j], a0, bf[j][0]);
            mma16816(c[j], a1, bf[j][1]);
        }

        // ---- epilogue: relu + w2 dot ----
        float simA = 0.f, simB = 0.f;
        #pragma unroll
        for (int j = 0; j < 8; j++) {
            simA = fmaf(w2a[j], fmaxf(c[j][0], 0.f), simA);
            simA = fmaf(w2b[j], fmaxf(c[j][1], 0.f), simA);
            simB = fmaf(w2a[j], fmaxf(c[j][2], 0.f), simB);
            simB = fmaf(w2b[j], fmaxf(c[j][3], 0.f), simB);
        }
        simA += __shfl_xor_sync(0xFFFFFFFFu, simA, 1);
        simA += __shfl_xor_sync(0xFFFFFFFFu, simA, 2);
        simB += __shfl_xor_sync(0xFFFFFFFFu, simB, 1);
        simB += __shfl_xor_sync(0xFFFFFFFFu, simB, 2);

        if ((lane & 3) == 0) {
            const int g = lane >> 2;
            #pragma unroll
            for (int half = 0; half < 2; half++) {
                int row = g + half * 8;
                float sim = (half ? simB : simA) + my_b2;
                int pix2 = pixbase + row;
                int bb = pix2 >> 16;
                int hw = pix2 & 65535;
                float res = cenC[warp][row] / (1.f + __expf(-sim));
                g_comb[((size_t)(bb * CHn + srcch) << 16) + hw] = res;
                if (n == 0)
                    g_comb[((size_t)(bb * CHn + 3) << 16) + hw] = cenB[warp][row];
            }
        }
        __syncwarp();   // protect cen/As reuse next iteration
    }
}

// ---------------------------------------------------------------------------
// Kernel 2: final 7->7 3x3 SAME conv, fp32 (R1 config — measured 25.9 us).
// ---------------------------------------------------------------------------
__global__ __launch_bounds__(256, 4) void mix_kernel(
    const float* __restrict__ Wm, const float* __restrict__ bm,
    float* __restrict__ out)
{
    __shared__ float Wms[7 * 7 * 9];
    __shared__ float bms[7];

    const int tid = threadIdx.y * 64 + threadIdx.x;
    for (int i = tid; i < 7 * 7 * 9; i += 256) Wms[i] = Wm[i];
    if (tid < 7) bms[tid] = bm[tid];
    __syncthreads();

    const int b  = blockIdx.y;
    const int h  = blockIdx.x * 4 + threadIdx.y;
    const int w0 = threadIdx.x * PX;

    float acc[7][PX];
    #pragma unroll
    for (int o = 0; o < 7; o++) {
        const float bv = bms[o];
        #pragma unroll
        for (int p = 0; p < PX; p++) acc[o][p] = bv;
    }

    #pragma unroll 1
    for (int ic = 0; ic < 7; ic++) {
        const float* xp = g_comb + ((size_t)(b * CHn + ic)) * Hn * Wn;
        float win[3][PX + 2];
        #pragma unroll
        for (int r = 0; r < 3; r++) {
            int hh = h - 1 + r;
            bool hok = (hh >= 0) && (hh < Hn);
            #pragma unroll
            for (int c = 0; c < PX + 2; c++) {
                int ww = w0 - 1 + c;
                win[r][c] = (hok && ww >= 0 && ww < Wn) ? xp[hh * Wn + ww] : 0.f;
            }
        }
        #pragma unroll
        for (int o = 0; o < 7; o++) {
            #pragma unroll
            for (int kh = 0; kh < 3; kh++) {
                #pragma unroll
                for (int kw = 0; kw < 3; kw++) {
                    const float wv = Wms[(o * 7 + ic) * 9 + kh * 3 + kw];
                    #pragma unroll
                    for (int p = 0; p < PX; p++)
                        acc[o][p] = fmaf(wv, win[kh][kw + p], acc[o][p]);
                }
            }
        }
    }

    #pragma unroll
    for (int o = 0; o < 7; o++) {
        float4 v = make_float4(acc[o][0], acc[o][1], acc[o][2], acc[o][3]);
        *(float4*)(out + (((size_t)(b * CHn + o)) * Hn + h) * Wn + w0) = v;
    }
}

// ---------------------------------------------------------------------------
// kernel_launch: graph-capturable, allocation-free.
// Input order (metadata): x, W1, b1, W2, b2, Wm, bm
// ---------------------------------------------------------------------------
extern "C" void kernel_launch(void* const* d_in, const int* in_sizes, int n_in,
                              void* d_out, int out_size)
{
    const float* x  = (const float*)d_in[0];
    const float* W1 = (const float*)d_in[1];
    const float* b1 = (const float*)d_in[2];
    const float* W2 = (const float*)d_in[3];
    const float* b2 = (const float*)d_in[4];
    const float* Wm = (const float*)d_in[5];
    const float* bm = (const float*)d_in[6];
    float* out = (float*)d_out;

    dim3 gridB(CTAS_PER_BRANCH, NBR, 1);
    branch_kernel<<<gridB, 128>>>(x, W1, b1, W2, b2);

    dim3 blockM(64, 4, 1);
    dim3 gridM(Hn / 4, Bn, 1);
    mix_kernel<<<gridM, blockM>>>(Wm, bm, out);
}